// round 13
// baseline (speedup 1.0000x reference)
#include <cuda_runtime.h>
#include <cstdint>

// TopologyTracker: 64x64 histogram of (prev, curr) transitions over 16.7M events.
// Output layout (float32): [0..4095] = transitions + counts, [4096] = total + N.
//
// R13: R11's floor-bound core (296x512, 2 CTAs/SM, 16 ev/iter, 8 front-
// batched LDG.128) + WORK-STEALING: static grid-stride partitioning exposed
// the per-SM speed spread (~1.1x, near/far L2 die) as a ~2.5us straggler
// tail in single-wave configs. A global ticket hands out 512 chunks of 32K
// events; fast SMs take more. Ticket/done counters self-reset (total grabs
// per launch is deterministic: NCHUNK + GRID) -> graph-replay safe.

#define NUM_TILES 64
#define NUM_BINS  (NUM_TILES * NUM_TILES)   // 4096
#define THREADS   512
#define GRID      296                        // 2 CTAs/SM * 148 SMs
#define CHUNK_ITERS 2048                     // 2048 iters * 16 ev = 32K events

__device__ unsigned int g_ticket;   // zero-init; self-reset each launch
__device__ unsigned int g_done;     // zero-init; self-reset each launch

__global__ void __launch_bounds__(THREADS, 2)
tt_hist(const int* __restrict__ prev,
        const int* __restrict__ curr,
        const float* __restrict__ trans_in,
        const float* __restrict__ total_in,
        float* __restrict__ out,
        int out_size,
        int n)
{
    __shared__ int h[NUM_BINS];
    __shared__ unsigned int s_chunk;

    #pragma unroll
    for (int i = threadIdx.x; i < NUM_BINS; i += THREADS) {
        h[i] = 0;
    }
    __syncthreads();

    const int4* __restrict__ p4 = reinterpret_cast<const int4*>(prev);
    const int4* __restrict__ c4 = reinterpret_cast<const int4*>(curr);

    const int n16    = n >> 4;                                   // 16-ev iters
    const unsigned int nchunk = (unsigned int)((n16 + CHUNK_ITERS - 1) / CHUNK_ITERS);

    // ---- work-stealing main loop ----
    for (;;) {
        if (threadIdx.x == 0) {
            s_chunk = atomicAdd(&g_ticket, 1u);
        }
        __syncthreads();
        const unsigned int c = s_chunk;
        __syncthreads();              // protect s_chunk before next grab
        if (c >= nchunk) break;

        const int base = (int)c * CHUNK_ITERS;
        const int end  = min(base + CHUNK_ITERS, n16);

        for (int i = base + threadIdx.x; i < end; i += THREADS) {
            int4 pa = p4[4 * i];
            int4 pb = p4[4 * i + 1];
            int4 pc = p4[4 * i + 2];
            int4 pd = p4[4 * i + 3];
            int4 ca = c4[4 * i];
            int4 cb = c4[4 * i + 1];
            int4 cc = c4[4 * i + 2];
            int4 cd = c4[4 * i + 3];

            atomicAdd(&h[(pa.x << 6) + ca.x], 1);
            atomicAdd(&h[(pa.y << 6) + ca.y], 1);
            atomicAdd(&h[(pa.z << 6) + ca.z], 1);
            atomicAdd(&h[(pa.w << 6) + ca.w], 1);
            atomicAdd(&h[(pb.x << 6) + cb.x], 1);
            atomicAdd(&h[(pb.y << 6) + cb.y], 1);
            atomicAdd(&h[(pb.z << 6) + cb.z], 1);
            atomicAdd(&h[(pb.w << 6) + cb.w], 1);
            atomicAdd(&h[(pc.x << 6) + cc.x], 1);
            atomicAdd(&h[(pc.y << 6) + cc.y], 1);
            atomicAdd(&h[(pc.z << 6) + cc.z], 1);
            atomicAdd(&h[(pc.w << 6) + cc.w], 1);
            atomicAdd(&h[(pd.x << 6) + cd.x], 1);
            atomicAdd(&h[(pd.y << 6) + cd.y], 1);
            atomicAdd(&h[(pd.z << 6) + cd.z], 1);
            atomicAdd(&h[(pd.w << 6) + cd.w], 1);
        }
    }

    // Scalar tail (n % 16; N = 16777216 divisible, kept for safety).
    {
        const int tid    = blockIdx.x * THREADS + threadIdx.x;
        const int stride = GRID * THREADS;
        for (int i = (n16 << 4) + tid; i < n; i += stride) {
            atomicAdd(&h[(prev[i] << 6) + curr[i]], 1);
        }
    }

    __syncthreads();

    // Flush onto memset-zeroed out; staggered start per CTA across L2 lines.
    // CTA 0 folds in trans_in (must not skip zero bins) and the total.
    const int off = (blockIdx.x << 5) & (NUM_BINS - 1);
    if (blockIdx.x == 0) {
        #pragma unroll
        for (int j = threadIdx.x; j < NUM_BINS; j += THREADS) {
            int i = (j + off) & (NUM_BINS - 1);
            atomicAdd(&out[i], (float)h[i] + trans_in[i]);
        }
        if (threadIdx.x == 0 && NUM_BINS < out_size) {
            atomicAdd(&out[NUM_BINS], total_in[0] + (float)n);
        }
    } else {
        #pragma unroll
        for (int j = threadIdx.x; j < NUM_BINS; j += THREADS) {
            int i = (j + off) & (NUM_BINS - 1);
            int v = h[i];
            if (v != 0) {
                atomicAdd(&out[i], (float)v);
            }
        }
    }

    // Reset the stealing counters for the next graph replay. All grabs in
    // this launch are complete (every CTA broke out), so writing g_ticket
    // here races with nothing; kernel-end makes it visible to next launch.
    __threadfence();
    __syncthreads();
    if (threadIdx.x == 0) {
        unsigned int d = atomicAdd(&g_done, 1u);
        if (d == (unsigned int)(GRID - 1)) {
            g_ticket = 0;
            g_done   = 0;
        }
    }
}

// ---------------------------------------------------------------------------
// Launcher: memset node zeroes out, then one hist kernel does everything.
// ---------------------------------------------------------------------------
extern "C" void kernel_launch(void* const* d_in, const int* in_sizes, int n_in,
                              void* d_out, int out_size)
{
    const int*   prev     = (const int*)  d_in[0];
    const int*   curr     = (const int*)  d_in[1];
    const float* trans_in = (const float*)d_in[2];
    const float* total_in = (const float*)d_in[3];
    float*       out      = (float*)d_out;

    const int n = in_sizes[0];

    // Zero the output (graph-capturable memset node).
    cudaMemsetAsync(d_out, 0, (size_t)out_size * sizeof(float), 0);

    tt_hist<<<GRID, THREADS>>>(prev, curr, trans_in, total_in, out,
                               out_size, n);
}

// round 14
// speedup vs baseline: 1.2471x; 1.2471x over previous
#include <cuda_runtime.h>
#include <cstdint>

// TopologyTracker: 64x64 histogram of (prev, curr) transitions over 16.7M events.
// Output layout (float32): [0..4095] = transitions + counts, [4096] = total + N.
//
// R14: the workload is pinned to the smem-ATOMS floor (1 lane/event;
// ~29.15us at sustained clock — two independent kernels measured exactly
// that). Config: 3 CTAs/SM x 512 threads (24 warps/SM; reg budget 42),
// 8 events/iter with 4 front-batched LDG.128 (~32 regs, no register cliff).
// Wrapper: graph memset node zeroes out; CTA 0 folds trans_in/total into
// its flush; flush staggered per CTA across L2 lines.

#define NUM_TILES 64
#define NUM_BINS  (NUM_TILES * NUM_TILES)   // 4096
#define THREADS   512
#define GRID      444                        // 3 CTAs/SM * 148 SMs

__global__ void __launch_bounds__(THREADS, 3)
tt_hist(const int* __restrict__ prev,
        const int* __restrict__ curr,
        const float* __restrict__ trans_in,
        const float* __restrict__ total_in,
        float* __restrict__ out,
        int out_size,
        int n)
{
    __shared__ int h[NUM_BINS];

    #pragma unroll
    for (int i = threadIdx.x; i < NUM_BINS; i += THREADS) {
        h[i] = 0;
    }
    __syncthreads();

    const int tid    = blockIdx.x * THREADS + threadIdx.x;
    const int stride = gridDim.x * THREADS;

    const int4* __restrict__ p4 = reinterpret_cast<const int4*>(prev);
    const int4* __restrict__ c4 = reinterpret_cast<const int4*>(curr);

    // 8 events per iteration: 4 front-batched 16B loads (2 per stream).
    const int n8 = n >> 3;
    for (int i = tid; i < n8; i += stride) {
        int4 pa = p4[2 * i];
        int4 pb = p4[2 * i + 1];
        int4 ca = c4[2 * i];
        int4 cb = c4[2 * i + 1];

        atomicAdd(&h[(pa.x << 6) + ca.x], 1);
        atomicAdd(&h[(pa.y << 6) + ca.y], 1);
        atomicAdd(&h[(pa.z << 6) + ca.z], 1);
        atomicAdd(&h[(pa.w << 6) + ca.w], 1);
        atomicAdd(&h[(pb.x << 6) + cb.x], 1);
        atomicAdd(&h[(pb.y << 6) + cb.y], 1);
        atomicAdd(&h[(pb.z << 6) + cb.z], 1);
        atomicAdd(&h[(pb.w << 6) + cb.w], 1);
    }

    // Scalar tail (n % 8; N = 16777216 divisible, kept for safety).
    for (int i = (n8 << 3) + tid; i < n; i += stride) {
        atomicAdd(&h[(prev[i] << 6) + curr[i]], 1);
    }

    __syncthreads();

    // Flush onto memset-zeroed out; staggered start per CTA so concurrent
    // CTAs hit different 128B L2 lines. CTA 0 folds in trans_in (must not
    // skip zero-count bins) and the total scalar.
    const int off = (blockIdx.x << 5) & (NUM_BINS - 1);
    if (blockIdx.x == 0) {
        #pragma unroll
        for (int j = threadIdx.x; j < NUM_BINS; j += THREADS) {
            int i = (j + off) & (NUM_BINS - 1);
            atomicAdd(&out[i], (float)h[i] + trans_in[i]);
        }
        if (threadIdx.x == 0 && NUM_BINS < out_size) {
            atomicAdd(&out[NUM_BINS], total_in[0] + (float)n);
        }
    } else {
        #pragma unroll
        for (int j = threadIdx.x; j < NUM_BINS; j += THREADS) {
            int i = (j + off) & (NUM_BINS - 1);
            int v = h[i];
            if (v != 0) {
                atomicAdd(&out[i], (float)v);
            }
        }
    }
}

// ---------------------------------------------------------------------------
// Launcher: memset node zeroes out, then one hist kernel does everything.
// ---------------------------------------------------------------------------
extern "C" void kernel_launch(void* const* d_in, const int* in_sizes, int n_in,
                              void* d_out, int out_size)
{
    const int*   prev     = (const int*)  d_in[0];
    const int*   curr     = (const int*)  d_in[1];
    const float* trans_in = (const float*)d_in[2];
    const float* total_in = (const float*)d_in[3];
    float*       out      = (float*)d_out;

    const int n = in_sizes[0];

    // Zero the output (graph-capturable memset node).
    cudaMemsetAsync(d_out, 0, (size_t)out_size * sizeof(float), 0);

    tt_hist<<<GRID, THREADS>>>(prev, curr, trans_in, total_in, out,
                               out_size, n);
}